// round 1
// baseline (speedup 1.0000x reference)
#include <cuda_runtime.h>
#include <cuda_bf16.h>
#include <cstdint>
#include <cstddef>

// Problem constants
#define T 4096      // tokens (B*S = 2*2048)
#define D 1024      // hidden dim
#define F 768       // ffn dim
#define E 64        // experts
#define K 8         // top-k
#define P (T*K)     // expanded pairs = 32768

#define BM 64
#define BN 64
#define BK 32
#define MAX_TILES (P/BM + E)   // 576

// ---------------- scratch (static device globals; no allocation) ----------------
__device__ float d_logits[T*E];
__device__ int   d_topk_ids[P];
__device__ float d_topk_w[P];
__device__ int   d_counts[E];
__device__ int   d_offsets[E+1];
__device__ int   d_cursor[E];
__device__ int   d_pair_token[P];
__device__ int   d_pair_slot[P];
__device__ float d_pair_w[P];
__device__ int   d_tile_expert[MAX_TILES];
__device__ int   d_tile_rowstart[MAX_TILES];
__device__ int   d_tile_rows[MAX_TILES];
__device__ int   d_num_tiles;
__device__ float d_h[(size_t)P * F];      // ~100 MB
__device__ float d_slots[(size_t)P * D];  // ~134 MB

// ---------------- kernels ----------------

__global__ void zero_counts_kernel() {
    if (threadIdx.x < E) d_counts[threadIdx.x] = 0;
}

// logits[T,E] = x[T,D] @ gate_w[E,D]^T   (tiled fp32)
__global__ void gate_gemm_kernel(const float* __restrict__ x,
                                 const float* __restrict__ gw) {
    __shared__ float As[BK][BM+1];
    __shared__ float Bs[BK][BN+1];
    int tid = threadIdx.x;
    int ty = tid / 16, tx = tid % 16;
    int m0 = blockIdx.x * BM;

    float acc[4][4];
    #pragma unroll
    for (int i=0;i<4;i++)
        #pragma unroll
        for (int j=0;j<4;j++) acc[i][j]=0.f;

    for (int k0 = 0; k0 < D; k0 += BK) {
        #pragma unroll
        for (int i = 0; i < 8; i++) {
            int l = tid + i*256;
            int m = l >> 5, k = l & 31;
            As[k][m] = x[(size_t)(m0+m)*D + k0 + k];
        }
        #pragma unroll
        for (int i = 0; i < 8; i++) {
            int l = tid + i*256;
            int n = l >> 5, k = l & 31;
            Bs[k][n] = gw[(size_t)n*D + k0 + k];
        }
        __syncthreads();
        #pragma unroll
        for (int k = 0; k < BK; k++) {
            float a[4], b[4];
            #pragma unroll
            for (int i=0;i<4;i++) a[i]=As[k][ty*4+i];
            #pragma unroll
            for (int j=0;j<4;j++) b[j]=Bs[k][tx*4+j];
            #pragma unroll
            for (int i=0;i<4;i++)
                #pragma unroll
                for (int j=0;j<4;j++) acc[i][j] += a[i]*b[j];
        }
        __syncthreads();
    }
    #pragma unroll
    for (int i=0;i<4;i++) {
        int m = m0 + ty*4 + i;
        #pragma unroll
        for (int j=0;j<4;j++)
            d_logits[(size_t)m*E + tx*4 + j] = acc[i][j];
    }
}

// warp-per-token: softmax over 64 logits, top-8 + renorm, count per expert
__global__ void topk_kernel() {
    int gwarp = (blockIdx.x * blockDim.x + threadIdx.x) >> 5;
    int lane = threadIdx.x & 31;
    if (gwarp >= T) return;
    float l0 = d_logits[(size_t)gwarp*E + lane];
    float l1 = d_logits[(size_t)gwarp*E + 32 + lane];
    float mx = fmaxf(l0, l1);
    #pragma unroll
    for (int o=16;o;o>>=1) mx = fmaxf(mx, __shfl_xor_sync(0xffffffffu, mx, o));
    float e0 = __expf(l0 - mx), e1 = __expf(l1 - mx);
    float s = e0 + e1;
    #pragma unroll
    for (int o=16;o;o>>=1) s += __shfl_xor_sync(0xffffffffu, s, o);
    float v0 = e0 / s, v1 = e1 / s;

    float tw[8]; int ti[8];
    float wsum = 0.f;
    #pragma unroll
    for (int it = 0; it < 8; it++) {
        float best; int bidx;
        if (v0 >= v1) { best = v0; bidx = lane; }
        else          { best = v1; bidx = lane + 32; }
        #pragma unroll
        for (int o=16;o;o>>=1) {
            float ov = __shfl_xor_sync(0xffffffffu, best, o);
            int   oi = __shfl_xor_sync(0xffffffffu, bidx, o);
            if (ov > best || (ov == best && oi < bidx)) { best = ov; bidx = oi; }
        }
        tw[it] = best; ti[it] = bidx;
        if (bidx == lane)      v0 = -1.f;
        if (bidx == lane + 32) v1 = -1.f;
        wsum += best;
    }
    if (lane == 0) {
        float inv = 1.f / (wsum + 1e-20f);
        #pragma unroll
        for (int i = 0; i < 8; i++) {
            d_topk_ids[gwarp*8 + i] = ti[i];
            d_topk_w[gwarp*8 + i]  = tw[i] * inv;
            atomicAdd(&d_counts[ti[i]], 1);
        }
    }
}

// serial scan + tile map (E=64, trivial)
__global__ void scan_kernel() {
    int off = 0, nt = 0;
    for (int e = 0; e < E; e++) {
        d_offsets[e] = off;
        d_cursor[e]  = off;
        int c = d_counts[e];
        for (int r = 0; r < c; r += BM) {
            d_tile_expert[nt]   = e;
            d_tile_rowstart[nt] = off + r;
            d_tile_rows[nt]     = (c - r < BM) ? (c - r) : BM;
            nt++;
        }
        off += c;
    }
    d_offsets[E] = off;
    d_num_tiles = nt;
}

__global__ void scatter_kernel() {
    int idx = blockIdx.x * blockDim.x + threadIdx.x;
    if (idx >= P) return;
    int e = d_topk_ids[idx];
    int pos = atomicAdd(&d_cursor[e], 1);
    d_pair_token[pos] = idx >> 3;
    d_pair_slot[pos]  = idx;
    d_pair_w[pos]     = d_topk_w[idx];
}

// h[rows,F] = silu(x_g @ Wg^T) * (x_g @ Wu^T), grouped by expert tile
__global__ void g1_kernel(const float* __restrict__ x,
                          const float* __restrict__ w_gate,
                          const float* __restrict__ w_up) {
    int tile = blockIdx.x;
    if (tile >= d_num_tiles) return;
    int e     = d_tile_expert[tile];
    int row0  = d_tile_rowstart[tile];
    int nrows = d_tile_rows[tile];
    int n0    = blockIdx.y * BN;
    const float* Bg = w_gate + (size_t)e * F * D;
    const float* Bu = w_up   + (size_t)e * F * D;

    __shared__ float As[BK][BM+1];
    __shared__ float Gs[BK][BN+1];
    __shared__ float Us[BK][BN+1];
    __shared__ int rowtok[BM];

    int tid = threadIdx.x;
    if (tid < BM)
        rowtok[tid] = (tid < nrows) ? d_pair_token[row0 + tid] : d_pair_token[row0];
    __syncthreads();

    int ty = tid / 16, tx = tid % 16;
    float ag[4][4], au[4][4];
    #pragma unroll
    for (int i=0;i<4;i++)
        #pragma unroll
        for (int j=0;j<4;j++) { ag[i][j]=0.f; au[i][j]=0.f; }

    for (int k0 = 0; k0 < D; k0 += BK) {
        #pragma unroll
        for (int i = 0; i < 8; i++) {
            int l = tid + i*256;
            int m = l >> 5, k = l & 31;
            As[k][m] = x[(size_t)rowtok[m]*D + k0 + k];
        }
        #pragma unroll
        for (int i = 0; i < 8; i++) {
            int l = tid + i*256;
            int n = l >> 5, k = l & 31;
            Gs[k][n] = Bg[(size_t)(n0+n)*D + k0 + k];
            Us[k][n] = Bu[(size_t)(n0+n)*D + k0 + k];
        }
        __syncthreads();
        #pragma unroll
        for (int k = 0; k < BK; k++) {
            float a[4], bg[4], bu[4];
            #pragma unroll
            for (int i=0;i<4;i++) a[i]=As[k][ty*4+i];
            #pragma unroll
            for (int j=0;j<4;j++){ bg[j]=Gs[k][tx*4+j]; bu[j]=Us[k][tx*4+j]; }
            #pragma unroll
            for (int i=0;i<4;i++)
                #pragma unroll
                for (int j=0;j<4;j++){ ag[i][j] += a[i]*bg[j]; au[i][j] += a[i]*bu[j]; }
        }
        __syncthreads();
    }
    #pragma unroll
    for (int i=0;i<4;i++) {
        int m = ty*4 + i;
        if (m < nrows) {
            #pragma unroll
            for (int j=0;j<4;j++) {
                float g = ag[i][j], u = au[i][j];
                float h = g / (1.f + __expf(-g)) * u;
                d_h[(size_t)(row0+m)*F + n0 + tx*4 + j] = h;
            }
        }
    }
}

// slots[slot,D] = pair_w * (h @ Wd^T), grouped by expert tile
__global__ void g2_kernel(const float* __restrict__ w_down) {
    int tile = blockIdx.x;
    if (tile >= d_num_tiles) return;
    int e     = d_tile_expert[tile];
    int row0  = d_tile_rowstart[tile];
    int nrows = d_tile_rows[tile];
    int n0    = blockIdx.y * BN;
    const float* Bd = w_down + (size_t)e * D * F;

    __shared__ float As[BK][BM+1];
    __shared__ float Bs[BK][BN+1];

    int tid = threadIdx.x;
    int ty = tid / 16, tx = tid % 16;
    float acc[4][4];
    #pragma unroll
    for (int i=0;i<4;i++)
        #pragma unroll
        for (int j=0;j<4;j++) acc[i][j]=0.f;

    for (int k0 = 0; k0 < F; k0 += BK) {
        #pragma unroll
        for (int i = 0; i < 8; i++) {
            int l = tid + i*256;
            int m = l >> 5, k = l & 31;
            int r = (m < nrows) ? (row0 + m) : row0;
            As[k][m] = d_h[(size_t)r*F + k0 + k];
        }
        #pragma unroll
        for (int i = 0; i < 8; i++) {
            int l = tid + i*256;
            int n = l >> 5, k = l & 31;
            Bs[k][n] = Bd[(size_t)(n0+n)*F + k0 + k];
        }
        __syncthreads();
        #pragma unroll
        for (int k = 0; k < BK; k++) {
            float a[4], b[4];
            #pragma unroll
            for (int i=0;i<4;i++) a[i]=As[k][ty*4+i];
            #pragma unroll
            for (int j=0;j<4;j++) b[j]=Bs[k][tx*4+j];
            #pragma unroll
            for (int i=0;i<4;i++)
                #pragma unroll
                for (int j=0;j<4;j++) acc[i][j] += a[i]*b[j];
        }
        __syncthreads();
    }
    #pragma unroll
    for (int i=0;i<4;i++) {
        int m = ty*4 + i;
        if (m < nrows) {
            int slot = d_pair_slot[row0 + m];
            float w  = d_pair_w[row0 + m];
            #pragma unroll
            for (int j=0;j<4;j++)
                d_slots[(size_t)slot*D + n0 + tx*4 + j] = w * acc[i][j];
        }
    }
}

// y[t,d] = sum_k slots[t*8+k, d]   (deterministic combine)
__global__ void combine_kernel(float* __restrict__ y) {
    int idx = blockIdx.x * blockDim.x + threadIdx.x;
    if (idx >= T*D) return;
    int t = idx / D, dd = idx % D;
    float s = 0.f;
    #pragma unroll
    for (int k = 0; k < 8; k++)
        s += d_slots[((size_t)t*8 + k)*D + dd];
    y[idx] = s;
}

// ---------------- launch ----------------
extern "C" void kernel_launch(void* const* d_in, const int* in_sizes, int n_in,
                              void* d_out, int out_size) {
    const float* x  = (const float*)d_in[0];
    const float* gw = (const float*)d_in[1];
    const float* wg = (const float*)d_in[2];
    const float* wu = (const float*)d_in[3];
    const float* wd = (const float*)d_in[4];
    float* y = (float*)d_out;

    zero_counts_kernel<<<1, 64>>>();
    gate_gemm_kernel<<<T/BM, 256>>>(x, gw);
    topk_kernel<<<T/4, 128>>>();
    scan_kernel<<<1, 1>>>();
    scatter_kernel<<<P/256, 256>>>();
    g1_kernel<<<dim3(MAX_TILES, F/BN), 256>>>(x, wg, wu);
    g2_kernel<<<dim3(MAX_TILES, D/BN), 256>>>(wd);
    combine_kernel<<<(T*D)/256, 256>>>(y);
}

// round 4
// speedup vs baseline: 2.6881x; 2.6881x over previous
#include <cuda_runtime.h>
#include <cuda_bf16.h>
#include <cstdint>
#include <cstddef>

// ---------------- problem constants ----------------
#define T 4096
#define D 1024
#define F 768
#define E 64
#define TOPK 8
#define P (T*TOPK)          // 32768

#define GM 128              // M tile
#define GN 128              // N tile
#define KC 32               // K chunk (bf16 elems)
#define NT_MAX (P/GM + E)   // 320

#define NC1 (D/KC)          // 32
#define NC2 (F/KC)          // 24

#define RSTRIDE 80          // smem row stride bytes (64B data + 16B skew)
#define TILE_SB (128*RSTRIDE)       // 10240
#define STAGE1 (6*TILE_SB)          // A_hi A_lo G_hi G_lo U_hi U_lo
#define STAGE2 (4*TILE_SB)          // A_hi A_lo B_hi B_lo
#define SMEM_G1 (2*STAGE1)          // 122880
#define SMEM_G2 (2*STAGE2)          // 81920

// ---------------- device scratch ----------------
__device__ float d_logits[T*E];
__device__ int   d_topk_ids[P];
__device__ float d_topk_w[P];
__device__ int   d_counts[E];
__device__ int   d_cursor[E];
__device__ int   d_pair_token[P];
__device__ int   d_pair_slot[P];
__device__ float d_pair_w[P];
__device__ int   d_tile_expert[NT_MAX];
__device__ int   d_tile_rowstart[NT_MAX];
__device__ int   d_tile_rows[NT_MAX];
__device__ int   d_num_tiles;

__device__ __align__(16) __nv_bfloat16 d_x_hi[(size_t)T*D];
__device__ __align__(16) __nv_bfloat16 d_x_lo[(size_t)T*D];
__device__ __align__(16) __nv_bfloat16 d_wg_hi[(size_t)E*F*D];
__device__ __align__(16) __nv_bfloat16 d_wg_lo[(size_t)E*F*D];
__device__ __align__(16) __nv_bfloat16 d_wu_hi[(size_t)E*F*D];
__device__ __align__(16) __nv_bfloat16 d_wu_lo[(size_t)E*F*D];
__device__ __align__(16) __nv_bfloat16 d_wd_hi[(size_t)E*D*F];
__device__ __align__(16) __nv_bfloat16 d_wd_lo[(size_t)E*D*F];
__device__ __align__(16) __nv_bfloat16 d_h_hi[(size_t)P*F];
__device__ __align__(16) __nv_bfloat16 d_h_lo[(size_t)P*F];
__device__ __align__(16) float d_slots[(size_t)P*D];

// ---------------- helpers ----------------
__device__ __forceinline__ uint32_t smem_u32(const void* p) {
    uint32_t a;
    asm("{ .reg .u64 t; cvta.to.shared.u64 t, %1; cvt.u32.u64 %0, t; }" : "=r"(a) : "l"(p));
    return a;
}

#define CP16(dst, src) asm volatile("cp.async.cg.shared.global [%0], [%1], 16;" :: "r"(dst), "l"(src))
#define CP_COMMIT() asm volatile("cp.async.commit_group;" ::: "memory")
#define CP_WAIT0()  asm volatile("cp.async.wait_group 0;" ::: "memory")
#define CP_WAIT1()  asm volatile("cp.async.wait_group 1;" ::: "memory")

__device__ __forceinline__ void ldsm4(uint32_t* r, uint32_t a) {
    asm volatile("ldmatrix.sync.aligned.m8n8.x4.shared.b16 {%0,%1,%2,%3}, [%4];"
        : "=r"(r[0]), "=r"(r[1]), "=r"(r[2]), "=r"(r[3]) : "r"(a));
}
__device__ __forceinline__ void mma16816(float* d, const uint32_t* a, uint32_t b0, uint32_t b1) {
    asm volatile("mma.sync.aligned.m16n8k16.row.col.f32.bf16.bf16.f32 "
        "{%0,%1,%2,%3}, {%4,%5,%6,%7}, {%8,%9}, {%0,%1,%2,%3};"
        : "+f"(d[0]), "+f"(d[1]), "+f"(d[2]), "+f"(d[3])
        : "r"(a[0]), "r"(a[1]), "r"(a[2]), "r"(a[3]), "r"(b0), "r"(b1));
}

// fp32 -> (bf16 hi truncated, bf16 lo = rounded residual), packed x2
__device__ __forceinline__ void split2(float a, float b, uint32_t& hi, uint32_t& lo) {
    uint32_t ua = __float_as_uint(a), ub = __float_as_uint(b);
    hi = __byte_perm(ua, ub, 0x7632);
    float ra = a - __uint_as_float(ua & 0xffff0000u);
    float rb = b - __uint_as_float(ub & 0xffff0000u);
    asm("cvt.rn.satfinite.bf16x2.f32 %0, %1, %2;" : "=r"(lo) : "f"(rb), "f"(ra));
}

// ---------------- routing kernels ----------------
__global__ void zero_counts_kernel() {
    if (threadIdx.x < E) d_counts[threadIdx.x] = 0;
}

__global__ void gate_gemm_kernel(const float* __restrict__ x,
                                 const float* __restrict__ gw) {
    __shared__ float As[32][65];
    __shared__ float Bs[32][65];
    int tid = threadIdx.x;
    int ty = tid / 16, tx = tid % 16;
    int m0 = blockIdx.x * 64;
    float acc[4][4];
    #pragma unroll
    for (int i = 0; i < 4; i++) {
        #pragma unroll
        for (int j = 0; j < 4; j++) acc[i][j] = 0.f;
    }
    for (int k0 = 0; k0 < D; k0 += 32) {
        #pragma unroll
        for (int i = 0; i < 8; i++) {
            int l = tid + i*256; int m = l >> 5, k = l & 31;
            As[k][m] = x[(size_t)(m0+m)*D + k0 + k];
        }
        #pragma unroll
        for (int i = 0; i < 8; i++) {
            int l = tid + i*256; int n = l >> 5, k = l & 31;
            Bs[k][n] = gw[(size_t)n*D + k0 + k];
        }
        __syncthreads();
        #pragma unroll
        for (int k = 0; k < 32; k++) {
            float a[4], b[4];
            #pragma unroll
            for (int i = 0; i < 4; i++) a[i] = As[k][ty*4+i];
            #pragma unroll
            for (int j = 0; j < 4; j++) b[j] = Bs[k][tx*4+j];
            #pragma unroll
            for (int i = 0; i < 4; i++) {
                #pragma unroll
                for (int j = 0; j < 4; j++) acc[i][j] += a[i]*b[j];
            }
        }
        __syncthreads();
    }
    #pragma unroll
    for (int i = 0; i < 4; i++) {
        int m = m0 + ty*4 + i;
        #pragma unroll
        for (int j = 0; j < 4; j++)
            d_logits[(size_t)m*E + tx*4 + j] = acc[i][j];
    }
}

__global__ void topk_kernel() {
    int gwarp = (blockIdx.x * blockDim.x + threadIdx.x) >> 5;
    int lane = threadIdx.x & 31;
    if (gwarp >= T) return;
    float l0 = d_logits[(size_t)gwarp*E + lane];
    float l1 = d_logits[(size_t)gwarp*E + 32 + lane];
    float mx = fmaxf(l0, l1);
    #pragma unroll
    for (int o=16;o;o>>=1) mx = fmaxf(mx, __shfl_xor_sync(0xffffffffu, mx, o));
    float e0 = __expf(l0 - mx), e1 = __expf(l1 - mx);
    float s = e0 + e1;
    #pragma unroll
    for (int o=16;o;o>>=1) s += __shfl_xor_sync(0xffffffffu, s, o);
    float v0 = e0 / s, v1 = e1 / s;
    float tw[8]; int ti[8]; float wsum = 0.f;
    #pragma unroll
    for (int it = 0; it < 8; it++) {
        float best; int bidx;
        if (v0 >= v1) { best = v0; bidx = lane; }
        else          { best = v1; bidx = lane + 32; }
        #pragma unroll
        for (int o=16;o;o>>=1) {
            float ov = __shfl_xor_sync(0xffffffffu, best, o);
            int   oi = __shfl_xor_sync(0xffffffffu, bidx, o);
            if (ov > best || (ov == best && oi < bidx)) { best = ov; bidx = oi; }
        }
        tw[it] = best; ti[it] = bidx;
        if (bidx == lane)      v0 = -1.f;
        if (bidx == lane + 32) v1 = -1.f;
        wsum += best;
    }
    if (lane == 0) {
        float inv = 1.f / (wsum + 1e-20f);
        #pragma unroll
        for (int i = 0; i < 8; i++) {
            d_topk_ids[gwarp*8 + i] = ti[i];
            d_topk_w[gwarp*8 + i]  = tw[i] * inv;
            atomicAdd(&d_counts[ti[i]], 1);
        }
    }
}

__global__ void scan_kernel() {
    int off = 0, nt = 0;
    for (int e = 0; e < E; e++) {
        d_cursor[e] = off;
        int c = d_counts[e];
        for (int r = 0; r < c; r += GM) {
            d_tile_expert[nt]   = e;
            d_tile_rowstart[nt] = off + r;
            d_tile_rows[nt]     = (c - r < GM) ? (c - r) : GM;
            nt++;
        }
        off += c;
    }
    d_num_tiles = nt;
}

__global__ void scatter_kernel() {
    int idx = blockIdx.x * blockDim.x + threadIdx.x;
    if (idx >= P) return;
    int e = d_topk_ids[idx];
    int pos = atomicAdd(&d_cursor[e], 1);
    d_pair_token[pos] = idx >> 3;
    d_pair_slot[pos]  = idx;
    d_pair_w[pos]     = d_topk_w[idx];
}

__global__ void cvt_kernel(const float4* __restrict__ in,
                           uint2* __restrict__ hi, uint2* __restrict__ lo, int n4) {
    int stride = gridDim.x * blockDim.x;
    for (int i = blockIdx.x * blockDim.x + threadIdx.x; i < n4; i += stride) {
        float4 v = in[i];
        uint2 h, l;
        split2(v.x, v.y, h.x, l.x);
        split2(v.z, v.w, h.y, l.y);
        hi[i] = h; lo[i] = l;
    }
}

// ---------------- G1: h = silu(x@Wg^T)*(x@Wu^T) via mma.sync bf16 split ----------------
__global__ __launch_bounds__(256, 1)
void g1_mma_kernel() {
    extern __shared__ char smem[];
    __shared__ int rowtok_s[GM];
    int tile = blockIdx.x;
    if (tile >= d_num_tiles) return;
    int e     = d_tile_expert[tile];
    int row0  = d_tile_rowstart[tile];
    int nrows = d_tile_rows[tile];
    int n0    = blockIdx.y * GN;
    int tid = threadIdx.x;
    int lane = tid & 31, wid = tid >> 5;
    int wm = wid >> 2, wn = wid & 3;

    if (tid < GM) rowtok_s[tid] = d_pair_token[row0 + (tid < nrows ? tid : 0)];
    __syncthreads();

    uint32_t sb = smem_u32(smem);
    const __nv_bfloat16* Gh = d_wg_hi + (size_t)e * (F*D);
    const __nv_bfloat16* Gl = d_wg_lo + (size_t)e * (F*D);
    const __nv_bfloat16* Uh = d_wu_hi + (size_t)e * (F*D);
    const __nv_bfloat16* Ul = d_wu_lo + (size_t)e * (F*D);

    float accG[4][4][4], accU[4][4][4];
    #pragma unroll
    for (int i = 0; i < 4; i++)
        #pragma unroll
        for (int j = 0; j < 4; j++)
            #pragma unroll
            for (int q = 0; q < 4; q++) { accG[i][j][q] = 0.f; accU[i][j][q] = 0.f; }

    auto load_stage = [&](int cidx) {
        uint32_t stage = sb + (cidx & 1) * STAGE1;
        int koff = cidx * KC;
        #pragma unroll
        for (int it = 0; it < 12; it++) {
            int l = tid + it*256;
            int tl = l >> 9, rem = l & 511;
            int r = rem >> 2, c = rem & 3;
            uint32_t saddr = stage + tl*TILE_SB + r*RSTRIDE + c*16;
            const __nv_bfloat16* g;
            if (tl == 0)      g = d_x_hi + (size_t)rowtok_s[r]*D + koff + c*8;
            else if (tl == 1) g = d_x_lo + (size_t)rowtok_s[r]*D + koff + c*8;
            else {
                size_t wrow = (size_t)(n0 + r)*D + koff + c*8;
                g = (tl == 2) ? Gh + wrow : (tl == 3) ? Gl + wrow
                  : (tl == 4) ? Uh + wrow : Ul + wrow;
            }
            CP16(saddr, g);
        }
        CP_COMMIT();
    };

    load_stage(0);
    uint32_t laneoff = (uint32_t)((lane & 15)*RSTRIDE + (lane >> 4)*16);

    #pragma unroll 1
    for (int cidx = 0; cidx < NC1; cidx++) {
        if (cidx + 1 < NC1) { load_stage(cidx + 1); CP_WAIT1(); }
        else CP_WAIT0();
        __syncthreads();
        uint32_t base = sb + (cidx & 1) * STAGE1;
        #pragma unroll
        for (int kk = 0; kk < 2; kk++) {
            uint32_t ko = kk*32;
            uint32_t ah[4][4], al[4][4];
            uint32_t aHi = base + 0*TILE_SB + (wm*64)*RSTRIDE + ko + laneoff;
            uint32_t aLo = base + 1*TILE_SB + (wm*64)*RSTRIDE + ko + laneoff;
            #pragma unroll
            for (int i = 0; i < 4; i++) {
                ldsm4(ah[i], aHi + i*16*RSTRIDE);
                ldsm4(al[i], aLo + i*16*RSTRIDE);
            }
            uint32_t bh[2][4], bl[2][4];
            // ---- gate ----
            uint32_t gHi = base + 2*TILE_SB + (wn*32)*RSTRIDE + ko + laneoff;
            uint32_t gLo = base + 3*TILE_SB + (wn*32)*RSTRIDE + ko + laneoff;
            ldsm4(bh[0], gHi); ldsm4(bh[1], gHi + 16*RSTRIDE);
            ldsm4(bl[0], gLo); ldsm4(bl[1], gLo + 16*RSTRIDE);
            #pragma unroll
            for (int i = 0; i < 4; i++) {
                #pragma unroll
                for (int jj = 0; jj < 4; jj++) {
                    int gsel = jj >> 1, ssel = jj & 1;
                    uint32_t bh0 = bh[gsel][ssel], bh1 = bh[gsel][ssel+2];
                    uint32_t bl0 = bl[gsel][ssel], bl1 = bl[gsel][ssel+2];
                    mma16816(accG[i][jj], ah[i], bh0, bh1);
                    mma16816(accG[i][jj], al[i], bh0, bh1);
                    mma16816(accG[i][jj], ah[i], bl0, bl1);
                }
            }
            // ---- up ----
            uint32_t uHi = base + 4*TILE_SB + (wn*32)*RSTRIDE + ko + laneoff;
            uint32_t uLo = base + 5*TILE_SB + (wn*32)*RSTRIDE + ko + laneoff;
            ldsm4(bh[0], uHi); ldsm4(bh[1], uHi + 16*RSTRIDE);
            ldsm4(bl[0], uLo); ldsm4(bl[1], uLo + 16*RSTRIDE);
            #pragma unroll
            for (int i = 0; i < 4; i++) {
                #pragma unroll
                for (int jj = 0; jj < 4; jj++) {
                    int gsel = jj >> 1, ssel = jj & 1;
                    uint32_t bh0 = bh[gsel][ssel], bh1 = bh[gsel][ssel+2];
                    uint32_t bl0 = bl[gsel][ssel], bl1 = bl[gsel][ssel+2];
                    mma16816(accU[i][jj], ah[i], bh0, bh1);
                    mma16816(accU[i][jj], al[i], bh0, bh1);
                    mma16816(accU[i][jj], ah[i], bl0, bl1);
                }
            }
        }
        __syncthreads();
    }

    // epilogue: silu(g)*u -> bf16 hi/lo
    int rbase = wm*64, cb = wn*32;
    #pragma unroll
    for (int i = 0; i < 4; i++) {
        #pragma unroll
        for (int jj = 0; jj < 4; jj++) {
            #pragma unroll
            for (int half = 0; half < 2; half++) {
                int r = rbase + i*16 + (lane >> 2) + half*8;
                if (r < nrows) {
                    int col = n0 + cb + jj*8 + (lane & 3)*2;
                    float g0 = accG[i][jj][half*2],   g1 = accG[i][jj][half*2+1];
                    float u0 = accU[i][jj][half*2],   u1 = accU[i][jj][half*2+1];
                    float h0 = g0 / (1.f + __expf(-g0)) * u0;
                    float h1 = g1 / (1.f + __expf(-g1)) * u1;
                    uint32_t hi, lo;
                    split2(h0, h1, hi, lo);
                    size_t o = (size_t)(row0 + r)*F + col;
                    *(uint32_t*)&d_h_hi[o] = hi;
                    *(uint32_t*)&d_h_lo[o] = lo;
                }
            }
        }
    }
}

// ---------------- G2: slots = pair_w * (h @ Wd^T) ----------------
__global__ __launch_bounds__(256, 1)
void g2_mma_kernel() {
    extern __shared__ char smem[];
    int tile = blockIdx.x;
    if (tile >= d_num_tiles) return;
    int e     = d_tile_expert[tile];
    int row0  = d_tile_rowstart[tile];
    int nrows = d_tile_rows[tile];
    int n0    = blockIdx.y * GN;
    int tid = threadIdx.x;
    int lane = tid & 31, wid = tid >> 5;
    int wm = wid >> 2, wn = wid & 3;

    uint32_t sb = smem_u32(smem);
    const __nv_bfloat16* Bh = d_wd_hi + (size_t)e * (D*F);
    const __nv_bfloat16* Bl = d_wd_lo + (size_t)e * (D*F);

    float acc[4][4][4];
    #pragma unroll
    for (int i = 0; i < 4; i++)
        #pragma unroll
        for (int j = 0; j < 4; j++)
            #pragma unroll
            for (int q = 0; q < 4; q++) acc[i][j][q] = 0.f;

    auto load_stage = [&](int cidx) {
        uint32_t stage = sb + (cidx & 1) * STAGE2;
        int koff = cidx * KC;
        #pragma unroll
        for (int it = 0; it < 8; it++) {
            int l = tid + it*256;
            int tl = l >> 9, rem = l & 511;
            int r = rem >> 2, c = rem & 3;
            uint32_t saddr = stage + tl*TILE_SB + r*RSTRIDE + c*16;
            const __nv_bfloat16* g;
            if (tl < 2) {
                size_t arow = (size_t)(row0 + (r < nrows ? r : 0))*F + koff + c*8;
                g = (tl == 0) ? d_h_hi + arow : d_h_lo + arow;
            } else {
                size_t wrow = (size_t)(n0 + r)*F + koff + c*8;
                g = (tl == 2) ? Bh + wrow : Bl + wrow;
            }
            CP16(saddr, g);
        }
        CP_COMMIT();
    };

    load_stage(0);
    uint32_t laneoff = (uint32_t)((lane & 15)*RSTRIDE + (lane >> 4)*16);

    #pragma unroll 1
    for (int cidx = 0; cidx < NC2; cidx++) {
        if (cidx + 1 < NC2) { load_stage(cidx + 1); CP_WAIT1(); }
        else CP_WAIT0();
        __syncthreads();
        uint32_t base = sb + (cidx & 1) * STAGE2;
        #pragma unroll
        for (int kk = 0; kk < 2; kk++) {
            uint32_t ko = kk*32;
            uint32_t ah[4][4], al[4][4];
            uint32_t aHi = base + 0*TILE_SB + (wm*64)*RSTRIDE + ko + laneoff;
            uint32_t aLo = base + 1*TILE_SB + (wm*64)*RSTRIDE + ko + laneoff;
            #pragma unroll
            for (int i = 0; i < 4; i++) {
                ldsm4(ah[i], aHi + i*16*RSTRIDE);
                ldsm4(al[i], aLo + i*16*RSTRIDE);
            }
            uint32_t bh[2][4], bl[2][4];
            uint32_t wHi = base + 2*TILE_SB + (wn*32)*RSTRIDE + ko + laneoff;
            uint32_t wLo = base + 3*TILE_SB + (wn*32)*RSTRIDE + ko + laneoff;
            ldsm4(bh[0], wHi); ldsm4(bh[1], wHi + 16*RSTRIDE);
            ldsm4(bl[0], wLo); ldsm4(bl[1], wLo + 16*RSTRIDE);
            #pragma unroll
            for (int i = 0; i < 4; i++) {
                #pragma unroll
                for (int jj = 0; jj < 4; jj++) {
                    int gsel = jj >> 1, ssel = jj & 1;
                    uint32_t bh0 = bh[gsel][ssel], bh1 = bh[gsel][ssel+2];
                    uint32_t bl0 = bl[gsel][ssel], bl1 = bl[gsel][ssel+2];
                    mma16816(acc[i][jj], ah[i], bh0, bh1);
                    mma16816(acc[i][jj], al[i], bh0, bh1);
                    mma16816(acc[i][jj], ah[i], bl0, bl1);
                }
            }
        }
        __syncthreads();
    }

    int rbase = wm*64, cb = wn*32;
    #pragma unroll
    for (int i = 0; i < 4; i++) {
        #pragma unroll
        for (int jj = 0; jj < 4; jj++) {
            #pragma unroll
            for (int half = 0; half < 2; half++) {
                int r = rbase + i*16 + (lane >> 2) + half*8;
                if (r < nrows) {
                    int col = n0 + cb + jj*8 + (lane & 3)*2;
                    int slot = d_pair_slot[row0 + r];
                    float w  = d_pair_w[row0 + r];
                    float2 v;
                    v.x = acc[i][jj][half*2]   * w;
                    v.y = acc[i][jj][half*2+1] * w;
                    *(float2*)&d_slots[(size_t)slot*D + col] = v;
                }
            }
        }
    }
}

// y[t,d] = sum_k slots[t*8+k, d]
__global__ void combine_kernel(float* __restrict__ y) {
    int idx = blockIdx.x * blockDim.x + threadIdx.x;
    if (idx >= T*D) return;
    int t = idx / D, dd = idx % D;
    float s = 0.f;
    #pragma unroll
    for (int k = 0; k < 8; k++)
        s += d_slots[((size_t)t*8 + k)*D + dd];
    y[idx] = s;
}

// ---------------- launch ----------------
extern "C" void kernel_launch(void* const* d_in, const int* in_sizes, int n_in,
                              void* d_out, int out_size) {
    const float* x  = (const float*)d_in[0];
    const float* gw = (const float*)d_in[1];
    const float* wg = (const float*)d_in[2];
    const float* wu = (const float*)d_in[3];
    const float* wd = (const float*)d_in[4];
    float* y = (float*)d_out;

    cudaFuncSetAttribute(g1_mma_kernel, cudaFuncAttributeMaxDynamicSharedMemorySize, SMEM_G1);
    cudaFuncSetAttribute(g2_mma_kernel, cudaFuncAttributeMaxDynamicSharedMemorySize, SMEM_G2);

    __nv_bfloat16 *xh, *xl, *wgh, *wgl, *wuh, *wul, *wdh, *wdl;
    cudaGetSymbolAddress((void**)&xh,  d_x_hi);
    cudaGetSymbolAddress((void**)&xl,  d_x_lo);
    cudaGetSymbolAddress((void**)&wgh, d_wg_hi);
    cudaGetSymbolAddress((void**)&wgl, d_wg_lo);
    cudaGetSymbolAddress((void**)&wuh, d_wu_hi);
    cudaGetSymbolAddress((void**)&wul, d_wu_lo);
    cudaGetSymbolAddress((void**)&wdh, d_wd_hi);
    cudaGetSymbolAddress((void**)&wdl, d_wd_lo);

    zero_counts_kernel<<<1, 64>>>();
    gate_gemm_kernel<<<T/64, 256>>>(x, gw);
    topk_kernel<<<T/4, 128>>>();
    scan_kernel<<<1, 1>>>();
    scatter_kernel<<<P/256, 256>>>();

    const int WN4 = (E*F*D)/4;
    cvt_kernel<<<1184, 256>>>((const float4*)x,  (uint2*)xh,  (uint2*)xl,  (T*D)/4);
    cvt_kernel<<<2368, 256>>>((const float4*)wg, (uint2*)wgh, (uint2*)wgl, WN4);
    cvt_kernel<<<2368, 256>>>((const float4*)wu, (uint2*)wuh, (uint2*)wul, WN4);
    cvt_kernel<<<2368, 256>>>((const float4*)wd, (uint2*)wdh, (uint2*)wdl, WN4);

    g1_mma_kernel<<<dim3(NT_MAX, F/GN), 256, SMEM_G1>>>();
    g2_mma_kernel<<<dim3(NT_MAX, D/GN), 256, SMEM_G2>>>();
    combine_kernel<<<(T*D)/256, 256>>>(y);
}

// round 5
// speedup vs baseline: 3.4407x; 1.2800x over previous
#include <cuda_runtime.h>
#include <cuda_bf16.h>
#include <cstdint>
#include <cstddef>

// ---------------- problem constants ----------------
#define T 4096
#define D 1024
#define F 768
#define E 64
#define TOPK 8
#define P (T*TOPK)          // 32768

#define GM 128              // M tile
#define GN 128              // N tile
#define KC 32               // K chunk (fp32 elems) = 128B rows
#define NT_MAX (P/GM + E)   // 320

#define NC1 (D/KC)          // 32
#define NC2 (F/KC)          // 24

#define TB 16384            // tile bytes: 128 rows x 128B
#define STAGE1 (3*TB)       // A, G, U
#define STAGE2 (2*TB)       // A, B
#define SMEM_G1 (3*STAGE1)  // 147456 (3-stage pipeline)
#define SMEM_G2 (3*STAGE2)  // 98304

// ---------------- device scratch ----------------
__device__ float d_logits[T*E];
__device__ int   d_topk_ids[P];
__device__ float d_topk_w[P];
__device__ int   d_counts[E];
__device__ int   d_cursor[E];
__device__ int   d_pair_token[P];
__device__ int   d_pair_slot[P];
__device__ float d_pair_w[P];
__device__ int   d_tile_expert[NT_MAX];
__device__ int   d_tile_rowstart[NT_MAX];
__device__ int   d_tile_rows[NT_MAX];
__device__ int   d_num_tiles;

__device__ __align__(16) float d_h[(size_t)P*F];      // 100 MB fp32
__device__ __align__(16) float d_slots[(size_t)P*D];  // 134 MB

// ---------------- helpers ----------------
__device__ __forceinline__ uint32_t smem_u32(const void* p) {
    uint32_t a;
    asm("{ .reg .u64 t; cvta.to.shared.u64 t, %1; cvt.u32.u64 %0, t; }" : "=r"(a) : "l"(p));
    return a;
}

#define CP16(dst, src) asm volatile("cp.async.cg.shared.global [%0], [%1], 16;" :: "r"(dst), "l"(src))
#define CP_COMMIT() asm volatile("cp.async.commit_group;" ::: "memory")
#define CP_WAIT0()  asm volatile("cp.async.wait_group 0;" ::: "memory")
#define CP_WAIT1()  asm volatile("cp.async.wait_group 1;" ::: "memory")

__device__ __forceinline__ void mma16816(float* d, const uint32_t* a, uint32_t b0, uint32_t b1) {
    asm volatile("mma.sync.aligned.m16n8k16.row.col.f32.bf16.bf16.f32 "
        "{%0,%1,%2,%3}, {%4,%5,%6,%7}, {%8,%9}, {%0,%1,%2,%3};"
        : "+f"(d[0]), "+f"(d[1]), "+f"(d[2]), "+f"(d[3])
        : "r"(a[0]), "r"(a[1]), "r"(a[2]), "r"(a[3]), "r"(b0), "r"(b1));
}

// fp32 pair -> (bf16x2 hi truncated, bf16x2 lo = rounded residual)
__device__ __forceinline__ void split2(float a, float b, uint32_t& hi, uint32_t& lo) {
    uint32_t ua = __float_as_uint(a), ub = __float_as_uint(b);
    hi = __byte_perm(ua, ub, 0x7632);
    float ra = a - __uint_as_float(ua & 0xffff0000u);
    float rb = b - __uint_as_float(ub & 0xffff0000u);
    asm("cvt.rn.satfinite.bf16x2.f32 %0, %1, %2;" : "=r"(lo) : "f"(rb), "f"(ra));
}

// load fp32 pair (r, c),(r, c+1) from swizzled tile; produce bf16x2 hi/lo frags
__device__ __forceinline__ void ldfrag(uint32_t tile, int r, int c, uint32_t& hi, uint32_t& lo) {
    int ch = c >> 2;
    uint32_t addr = tile + r*128 + (uint32_t)((ch ^ ((r & 3) << 1)) << 4) + (uint32_t)((c & 3) << 2);
    float vx, vy;
    asm volatile("ld.shared.v2.f32 {%0,%1}, [%2];" : "=f"(vx), "=f"(vy) : "r"(addr));
    split2(vx, vy, hi, lo);
}

// ---------------- routing kernels ----------------
__global__ void zero_counts_kernel() {
    if (threadIdx.x < E) d_counts[threadIdx.x] = 0;
}

__global__ void gate_gemm_kernel(const float* __restrict__ x,
                                 const float* __restrict__ gw) {
    __shared__ float As[32][65];
    __shared__ float Bs[32][65];
    int tid = threadIdx.x;
    int ty = tid / 16, tx = tid % 16;
    int m0 = blockIdx.x * 64;
    float acc[4][4];
    #pragma unroll
    for (int i = 0; i < 4; i++) {
        #pragma unroll
        for (int j = 0; j < 4; j++) acc[i][j] = 0.f;
    }
    for (int k0 = 0; k0 < D; k0 += 32) {
        #pragma unroll
        for (int i = 0; i < 8; i++) {
            int l = tid + i*256; int m = l >> 5, k = l & 31;
            As[k][m] = x[(size_t)(m0+m)*D + k0 + k];
        }
        #pragma unroll
        for (int i = 0; i < 8; i++) {
            int l = tid + i*256; int n = l >> 5, k = l & 31;
            Bs[k][n] = gw[(size_t)n*D + k0 + k];
        }
        __syncthreads();
        #pragma unroll
        for (int k = 0; k < 32; k++) {
            float a[4], b[4];
            #pragma unroll
            for (int i = 0; i < 4; i++) a[i] = As[k][ty*4+i];
            #pragma unroll
            for (int j = 0; j < 4; j++) b[j] = Bs[k][tx*4+j];
            #pragma unroll
            for (int i = 0; i < 4; i++) {
                #pragma unroll
                for (int j = 0; j < 4; j++) acc[i][j] += a[i]*b[j];
            }
        }
        __syncthreads();
    }
    #pragma unroll
    for (int i = 0; i < 4; i++) {
        int m = m0 + ty*4 + i;
        #pragma unroll
        for (int j = 0; j < 4; j++)
            d_logits[(size_t)m*E + tx*4 + j] = acc[i][j];
    }
}

__global__ void topk_kernel() {
    int gwarp = (blockIdx.x * blockDim.x + threadIdx.x) >> 5;
    int lane = threadIdx.x & 31;
    if (gwarp >= T) return;
    float l0 = d_logits[(size_t)gwarp*E + lane];
    float l1 = d_logits[(size_t)gwarp*E + 32 + lane];
    float mx = fmaxf(l0, l1);
    #pragma unroll
    for (int o=16;o;o>>=1) mx = fmaxf(mx, __shfl_xor_sync(0xffffffffu, mx, o));
    float e0 = __expf(l0 - mx), e1 = __expf(l1 - mx);
    float s = e0 + e1;
    #pragma unroll
    for (int o=16;o;o>>=1) s += __shfl_xor_sync(0xffffffffu, s, o);
    float v0 = e0 / s, v1 = e1 / s;
    float tw[8]; int ti[8]; float wsum = 0.f;
    #pragma unroll
    for (int it = 0; it < 8; it++) {
        float best; int bidx;
        if (v0 >= v1) { best = v0; bidx = lane; }
        else          { best = v1; bidx = lane + 32; }
        #pragma unroll
        for (int o=16;o;o>>=1) {
            float ov = __shfl_xor_sync(0xffffffffu, best, o);
            int   oi = __shfl_xor_sync(0xffffffffu, bidx, o);
            if (ov > best || (ov == best && oi < bidx)) { best = ov; bidx = oi; }
        }
        tw[it] = best; ti[it] = bidx;
        if (bidx == lane)      v0 = -1.f;
        if (bidx == lane + 32) v1 = -1.f;
        wsum += best;
    }
    if (lane == 0) {
        float inv = 1.f / (wsum + 1e-20f);
        #pragma unroll
        for (int i = 0; i < 8; i++) {
            d_topk_ids[gwarp*8 + i] = ti[i];
            d_topk_w[gwarp*8 + i]  = tw[i] * inv;
            atomicAdd(&d_counts[ti[i]], 1);
        }
    }
}

__global__ void scan_kernel() {
    int off = 0, nt = 0;
    for (int e = 0; e < E; e++) {
        d_cursor[e] = off;
        int c = d_counts[e];
        for (int r = 0; r < c; r += GM) {
            d_tile_expert[nt]   = e;
            d_tile_rowstart[nt] = off + r;
            d_tile_rows[nt]     = (c - r < GM) ? (c - r) : GM;
            nt++;
        }
        off += c;
    }
    d_num_tiles = nt;
}

__global__ void scatter_kernel() {
    int idx = blockIdx.x * blockDim.x + threadIdx.x;
    if (idx >= P) return;
    int e = d_topk_ids[idx];
    int pos = atomicAdd(&d_cursor[e], 1);
    d_pair_token[pos] = idx >> 3;
    d_pair_slot[pos]  = idx;
    d_pair_w[pos]     = d_topk_w[idx];
}

// ---------------- G1: h = silu(x@Wg^T)*(x@Wu^T), fp32-in-smem, split-in-reg ----------------
__global__ __launch_bounds__(256, 1)
void g1_mma_kernel(const float* __restrict__ x,
                   const float* __restrict__ w_gate,
                   const float* __restrict__ w_up) {
    extern __shared__ char smem[];
    __shared__ int rowtok_s[GM];
    int tile = blockIdx.x;
    if (tile >= d_num_tiles) return;
    int e     = d_tile_expert[tile];
    int row0  = d_tile_rowstart[tile];
    int nrows = d_tile_rows[tile];
    int n0    = blockIdx.y * GN;
    int tid = threadIdx.x;
    int lane = tid & 31, wid = tid >> 5;
    int wm = wid >> 2, wn = wid & 3;

    if (tid < GM) rowtok_s[tid] = d_pair_token[row0 + (tid < nrows ? tid : 0)];
    __syncthreads();

    uint32_t sb = smem_u32(smem);
    const float* Wg = w_gate + (size_t)e * (F*D);
    const float* Wu = w_up   + (size_t)e * (F*D);

    float accG[4][4][4], accU[4][4][4];
    #pragma unroll
    for (int i = 0; i < 4; i++)
        #pragma unroll
        for (int j = 0; j < 4; j++)
            #pragma unroll
            for (int q = 0; q < 4; q++) { accG[i][j][q] = 0.f; accU[i][j][q] = 0.f; }

    auto load_stage = [&](int cidx) {
        uint32_t stage = sb + (cidx % 3) * STAGE1;
        int koff = cidx * KC;
        #pragma unroll
        for (int it = 0; it < 12; it++) {
            int tl = it >> 2;
            int rem = tid + (it & 3) * 256;
            int r = rem >> 3, ch = rem & 7;
            uint32_t dst = stage + tl*TB + r*128 + (uint32_t)((ch ^ ((r & 3) << 1)) << 4);
            const float* src;
            if (tl == 0)      src = x  + (size_t)rowtok_s[r]*D + koff + ch*4;
            else if (tl == 1) src = Wg + (size_t)(n0 + r)*D   + koff + ch*4;
            else              src = Wu + (size_t)(n0 + r)*D   + koff + ch*4;
            CP16(dst, src);
        }
        CP_COMMIT();
    };

    load_stage(0);
    load_stage(1);

    #pragma unroll 1
    for (int c = 0; c < NC1; c++) {
        if (c + 1 < NC1) CP_WAIT1(); else CP_WAIT0();
        __syncthreads();
        uint32_t base = sb + (c % 3) * STAGE1;
        #pragma unroll
        for (int kk = 0; kk < 2; kk++) {
            int cc = kk*16 + (lane & 3)*2;
            uint32_t ah[4][4], al[4][4];
            #pragma unroll
            for (int i = 0; i < 4; i++) {
                int rr = wm*64 + i*16 + (lane >> 2);
                ldfrag(base, rr,   cc,   ah[i][0], al[i][0]);
                ldfrag(base, rr+8, cc,   ah[i][1], al[i][1]);
                ldfrag(base, rr,   cc+8, ah[i][2], al[i][2]);
                ldfrag(base, rr+8, cc+8, ah[i][3], al[i][3]);
            }
            // gate
            #pragma unroll
            for (int j = 0; j < 4; j++) {
                int br = wn*32 + j*8 + (lane >> 2);
                uint32_t bh0, bl0, bh1, bl1;
                ldfrag(base + TB, br, cc,   bh0, bl0);
                ldfrag(base + TB, br, cc+8, bh1, bl1);
                #pragma unroll
                for (int i = 0; i < 4; i++) {
                    mma16816(accG[i][j], ah[i], bh0, bh1);
                    mma16816(accG[i][j], al[i], bh0, bh1);
                    mma16816(accG[i][j], ah[i], bl0, bl1);
                }
            }
            // up
            #pragma unroll
            for (int j = 0; j < 4; j++) {
                int br = wn*32 + j*8 + (lane >> 2);
                uint32_t bh0, bl0, bh1, bl1;
                ldfrag(base + 2*TB, br, cc,   bh0, bl0);
                ldfrag(base + 2*TB, br, cc+8, bh1, bl1);
                #pragma unroll
                for (int i = 0; i < 4; i++) {
                    mma16816(accU[i][j], ah[i], bh0, bh1);
                    mma16816(accU[i][j], al[i], bh0, bh1);
                    mma16816(accU[i][j], ah[i], bl0, bl1);
                }
            }
        }
        __syncthreads();
        if (c + 2 < NC1) load_stage(c + 2);
    }

    // epilogue: silu(g)*u -> fp32 h
    int rbase = wm*64, cb = wn*32;
    #pragma unroll
    for (int i = 0; i < 4; i++) {
        #pragma unroll
        for (int j = 0; j < 4; j++) {
            #pragma unroll
            for (int half = 0; half < 2; half++) {
                int r = rbase + i*16 + (lane >> 2) + half*8;
                if (r < nrows) {
                    int col = n0 + cb + j*8 + (lane & 3)*2;
                    float g0 = accG[i][j][half*2],   g1 = accG[i][j][half*2+1];
                    float u0 = accU[i][j][half*2],   u1 = accU[i][j][half*2+1];
                    float2 h;
                    h.x = g0 / (1.f + __expf(-g0)) * u0;
                    h.y = g1 / (1.f + __expf(-g1)) * u1;
                    *(float2*)&d_h[(size_t)(row0 + r)*F + col] = h;
                }
            }
        }
    }
}

// ---------------- G2: slots = pair_w * (h @ Wd^T) ----------------
__global__ __launch_bounds__(256, 1)
void g2_mma_kernel(const float* __restrict__ w_down) {
    extern __shared__ char smem[];
    int tile = blockIdx.x;
    if (tile >= d_num_tiles) return;
    int e     = d_tile_expert[tile];
    int row0  = d_tile_rowstart[tile];
    int nrows = d_tile_rows[tile];
    int n0    = blockIdx.y * GN;
    int tid = threadIdx.x;
    int lane = tid & 31, wid = tid >> 5;
    int wm = wid >> 2, wn = wid & 3;

    uint32_t sb = smem_u32(smem);
    const float* Wd = w_down + (size_t)e * (D*F);

    float acc[4][4][4];
    #pragma unroll
    for (int i = 0; i < 4; i++)
        #pragma unroll
        for (int j = 0; j < 4; j++)
            #pragma unroll
            for (int q = 0; q < 4; q++) acc[i][j][q] = 0.f;

    auto load_stage = [&](int cidx) {
        uint32_t stage = sb + (cidx % 3) * STAGE2;
        int koff = cidx * KC;
        #pragma unroll
        for (int it = 0; it < 8; it++) {
            int tl = it >> 2;
            int rem = tid + (it & 3) * 256;
            int r = rem >> 3, ch = rem & 7;
            uint32_t dst = stage + tl*TB + r*128 + (uint32_t)((ch ^ ((r & 3) << 1)) << 4);
            const float* src;
            if (tl == 0) src = d_h + (size_t)(row0 + (r < nrows ? r : 0))*F + koff + ch*4;
            else         src = Wd  + (size_t)(n0 + r)*F + koff + ch*4;
            CP16(dst, src);
        }
        CP_COMMIT();
    };

    load_stage(0);
    load_stage(1);

    #pragma unroll 1
    for (int c = 0; c < NC2; c++) {
        if (c + 1 < NC2) CP_WAIT1(); else CP_WAIT0();
        __syncthreads();
        uint32_t base = sb + (c % 3) * STAGE2;
        #pragma unroll
        for (int kk = 0; kk < 2; kk++) {
            int cc = kk*16 + (lane & 3)*2;
            uint32_t ah[4][4], al[4][4];
            #pragma unroll
            for (int i = 0; i < 4; i++) {
                int rr = wm*64 + i*16 + (lane >> 2);
                ldfrag(base, rr,   cc,   ah[i][0], al[i][0]);
                ldfrag(base, rr+8, cc,   ah[i][1], al[i][1]);
                ldfrag(base, rr,   cc+8, ah[i][2], al[i][2]);
                ldfrag(base, rr+8, cc+8, ah[i][3], al[i][3]);
            }
            #pragma unroll
            for (int j = 0; j < 4; j++) {
                int br = wn*32 + j*8 + (lane >> 2);
                uint32_t bh0, bl0, bh1, bl1;
                ldfrag(base + TB, br, cc,   bh0, bl0);
                ldfrag(base + TB, br, cc+8, bh1, bl1);
                #pragma unroll
                for (int i = 0; i < 4; i++) {
                    mma16816(acc[i][j], ah[i], bh0, bh1);
                    mma16816(acc[i][j], al[i], bh0, bh1);
                    mma16816(acc[i][j], ah[i], bl0, bl1);
                }
            }
        }
        __syncthreads();
        if (c + 2 < NC2) load_stage(c + 2);
    }

    int rbase = wm*64, cb = wn*32;
    #pragma unroll
    for (int i = 0; i < 4; i++) {
        #pragma unroll
        for (int j = 0; j < 4; j++) {
            #pragma unroll
            for (int half = 0; half < 2; half++) {
                int r = rbase + i*16 + (lane >> 2) + half*8;
                if (r < nrows) {
                    int col = n0 + cb + j*8 + (lane & 3)*2;
                    int slot = d_pair_slot[row0 + r];
                    float w  = d_pair_w[row0 + r];
                    float2 v;
                    v.x = acc[i][j][half*2]   * w;
                    v.y = acc[i][j][half*2+1] * w;
                    *(float2*)&d_slots[(size_t)slot*D + col] = v;
                }
            }
        }
    }
}

// y[t,d] = sum_k slots[t*8+k, d]
__global__ void combine_kernel(float* __restrict__ y) {
    int idx = blockIdx.x * blockDim.x + threadIdx.x;
    if (idx >= T*D) return;
    int t = idx / D, dd = idx % D;
    float s = 0.f;
    #pragma unroll
    for (int k = 0; k < 8; k++)
        s += d_slots[((size_t)t*8 + k)*D + dd];
    y[idx] = s;
}

// ---------------- launch ----------------
extern "C" void kernel_launch(void* const* d_in, const int* in_sizes, int n_in,
                              void* d_out, int out_size) {
    const float* x  = (const float*)d_in[0];
    const float* gw = (const float*)d_in[1];
    const float* wg = (const float*)d_in[2];
    const float* wu = (const float*)d_in[3];
    const float* wd = (const float*)d_in[4];
    float* y = (float*)d_out;

    cudaFuncSetAttribute(g1_mma_kernel, cudaFuncAttributeMaxDynamicSharedMemorySize, SMEM_G1);
    cudaFuncSetAttribute(g2_mma_kernel, cudaFuncAttributeMaxDynamicSharedMemorySize, SMEM_G2);

    zero_counts_kernel<<<1, 64>>>();
    gate_gemm_kernel<<<T/64, 256>>>(x, gw);
    topk_kernel<<<T/4, 128>>>();
    scan_kernel<<<1, 1>>>();
    scatter_kernel<<<P/256, 256>>>();

    g1_mma_kernel<<<dim3(NT_MAX, F/GN), 256, SMEM_G1>>>(x, wg, wu);
    g2_mma_kernel<<<dim3(NT_MAX, D/GN), 256, SMEM_G2>>>(wd);
    combine_kernel<<<(T*D)/256, 256>>>(y);
}